// round 5
// baseline (speedup 1.0000x reference)
#include <cuda_runtime.h>
#include <math.h>

// Problem constants
#define SS 64
#define BB 32
#define DM 586
#define DE 583
#define NL 4
#define K1 17
#define CO1 16
#define P1LEN 114
#define KP 21       // combined conv1+pool kernel length
#define CO2 8
#define P2LEN 38
#define CO3 32
#define T3 36
#define NV 128
#define XSTR 180    // smem x row stride in conv phase

#define NBLK 256
#define NTHR 128

// Scratch (no allocations allowed)
__device__ float g_x0[SS*BB*DM];
__device__ float g_rpart[SS*BB*2];                  // per row: {sum, sumsq}
__device__ __align__(16) float g_w1ps[BB*KP*16];    // [ci*21+m][16 co]
__device__ float g_wsum1[CO1];
__device__ float g_out1p[SS*CO1*P1LEN];
__device__ unsigned g_barA, g_barB;                  // monotonic barrier counters

// Grid-wide barrier: monotonic counter, wrap-safe, no reset needed across
// graph replays (target = next multiple of NBLK above this block's ticket).
__device__ __forceinline__ void grid_barrier(unsigned* ctr) {
    __threadfence();          // release: make this thread's global writes visible
    __syncthreads();
    if (threadIdx.x == 0) {
        unsigned t = atomicAdd(ctr, 1u);
        unsigned target = (t / NBLK + 1u) * NBLK;
        volatile unsigned* vp = (volatile unsigned*)ctr;
        while ((int)(*vp - target) < 0) { __nanosleep(64); }
    }
    __syncthreads();
    __threadfence();          // acquire
}

__global__ void __launch_bounds__(NTHR, 3)
kF(const int* __restrict__ tokens, const float* __restrict__ emb,
   const float* __restrict__ pos,
   const float* __restrict__ gamma, const float* __restrict__ beta,
   const float* __restrict__ w1, const float* __restrict__ b1,
   const float* __restrict__ w2, const float* __restrict__ b2,
   const float* __restrict__ w3, const float* __restrict__ b3,
   const float* __restrict__ wl, const float* __restrict__ bl,
   float* __restrict__ out) {
    extern __shared__ float smf[];
    int bx   = blockIdx.x;
    int tid  = threadIdx.x;
    int wid  = tid >> 5;
    int lane = tid & 31;

    // =====================================================================
    // Phase 1: embedding gather (*sqrt(D)) + pos -> g_x0, per-row partial
    // stats; blocks 0..15 additionally build combined conv1+pool weights.
    // =====================================================================
    {
        const float scale = sqrtf(586.0f);
        #pragma unroll
        for (int j = 0; j < 2; j++) {
            int r = bx*8 + wid*2 + j;          // row id = s*32 + b
            int tok = tokens[r];
            const float* row = emb + (size_t)tok * DE;
            float* xrow = g_x0 + (size_t)r * DM;
            float sum = 0.f, sq = 0.f;
            #pragma unroll
            for (int k = 0; k < 19; k++) {
                int d = lane + 32*k;
                if (d < DE) {
                    float v = row[d] * scale;
                    xrow[d] = v;
                    sum += v; sq += v*v;
                }
            }
            if (lane < 3) {
                float v = pos[r*3 + lane];
                xrow[DE + lane] = v;
                sum += v; sq += v*v;
            }
            #pragma unroll
            for (int off = 16; off >= 1; off >>= 1) {
                sum += __shfl_down_sync(0xffffffffu, sum, off);
                sq  += __shfl_down_sync(0xffffffffu, sq,  off);
            }
            if (lane == 0) { g_rpart[r*2] = sum; g_rpart[r*2+1] = sq; }
        }

        if (bx < CO1) {
            int co = bx;
            const float* wrow = w1 + co*BB*K1;   // 544 floats
            // w1p[ci][m] = 0.2 * sum_j w1[ci][m-j], j in [max(0,m-16), min(4,m)]
            for (int e = tid; e < BB*KP; e += NTHR) {
                int ci = e / KP;
                int m  = e - ci*KP;
                int jlo = m - (K1-1); if (jlo < 0) jlo = 0;
                int jhi = m;          if (jhi > 4) jhi = 4;
                float acc = 0.f;
                for (int j = jlo; j <= jhi; j++)
                    acc += wrow[ci*K1 + (m - j)];
                g_w1ps[e*16 + co] = acc * 0.2f;
            }
            // wsum1[co] = sum of all 544 raw weights (pooling coverage identity)
            float p = 0.f;
            for (int i = tid; i < BB*K1; i += NTHR) p += wrow[i];
            #pragma unroll
            for (int off = 16; off >= 1; off >>= 1)
                p += __shfl_down_sync(0xffffffffu, p, off);
            __shared__ float shw[4];
            if (lane == 0) shw[wid] = p;
            __syncthreads();
            if (tid == 0)
                g_wsum1[co] = shw[0] + shw[1] + shw[2] + shw[3];
        }
    }

    grid_barrier(&g_barA);

    // =====================================================================
    // Phase 2: fused conv1+avgpool1 as stride-5, K=21 conv on g_x0.
    // 256 tasks (64 s x 4 p-chunks of {29,29,28,28}).
    // Tile: 4 co x 1 p per thread; f32x2 packed FMA (co pairs), weights via
    // single LDS.128 per tap. BN affine computed inline, folded in epilogue.
    // =====================================================================
    {
        int s  = bx >> 2;
        int cc = bx & 3;
        int p0 = (cc < 2) ? cc*29 : 58 + (cc-2)*28;
        int CH = (cc < 2) ? 29 : 28;
        int d0 = p0 * 5;
        int span = (CH-1)*5 + KP;  // 161 or 156 valid input cols

        float* xs = smf;                    // BB * XSTR   (5760 floats)
        float* ws = smf + BB*XSTR;          // 672 * 16    (10752 floats)

        for (int idx = tid; idx < BB*XSTR; idx += NTHR) {
            int ci = idx / XSTR;
            int dd = idx - ci*XSTR;
            float v = 0.f;
            if (dd < span) v = g_x0[(s*BB + ci)*DM + d0 + dd];
            xs[idx] = v;
        }
        {
            const float4* wsrc = (const float4*)g_w1ps;
            float4* wdst = (float4*)ws;
            for (int idx = tid; idx < BB*KP*4; idx += NTHR) wdst[idx] = wsrc[idx];
        }
        __syncthreads();

        int pt  = tid >> 2;       // 0..31  (p position within chunk)
        int cop = tid & 3;        // 0..3   (group of 4 co)
        int co0 = cop * 4;
        unsigned long long acc01 = 0ull, acc23 = 0ull;  // packed (0.f,0.f)
        const float* xr0 = xs + 5*pt;
        const float* wp0 = ws + co0;
        #pragma unroll 2
        for (int ci = 0; ci < BB; ci++) {
            const float* xr = xr0 + ci*XSTR;
            const float* wp = wp0 + ci*KP*16;
            #pragma unroll
            for (int m = 0; m < KP; m++) {
                float xv = xr[m];
                unsigned long long xd;
                asm("mov.b64 %0, {%1, %1};" : "=l"(xd) : "r"(__float_as_uint(xv)));
                ulonglong2 wv = *(const ulonglong2*)(wp + m*16);
                asm("fma.rn.f32x2 %0, %1, %2, %3;" : "=l"(acc01) : "l"(wv.x), "l"(xd), "l"(acc01));
                asm("fma.rn.f32x2 %0, %1, %2, %3;" : "=l"(acc23) : "l"(wv.y), "l"(xd), "l"(acc23));
            }
        }
        // BN affine fold (redundant per thread; broadcast loads)
        float A, Cf;
        {
            float ts = 0.f, tq = 0.f;
            #pragma unroll
            for (int i = 0; i < BB; i++) {
                ts += g_rpart[(s*BB + i)*2];
                tq += g_rpart[(s*BB + i)*2 + 1];
            }
            float invN = 1.f / (float)(BB*DM);
            float m = ts * invN;
            float v = tq * invN - m*m;   // biased var, matches reference
            A = 1.f; Cf = 0.f;
            #pragma unroll
            for (int l = 0; l < NL; l++) {
                float g  = gamma[l*SS + s];
                float bb = beta[l*SS + s];
                float inv = rsqrtf(v + 1e-5f);
                float a = g * inv;
                float c = bb - a * m;
                A = a * A;
                Cf = a * Cf + c;
                m = bb;
                v = a * a * v;
            }
        }
        if (pt < CH) {
            int p = p0 + pt;
            unsigned u0, u1, u2, u3;
            asm("mov.b64 {%0, %1}, %2;" : "=r"(u0), "=r"(u1) : "l"(acc01));
            asm("mov.b64 {%0, %1}, %2;" : "=r"(u2), "=r"(u3) : "l"(acc23));
            float r[4] = { __uint_as_float(u0), __uint_as_float(u1),
                           __uint_as_float(u2), __uint_as_float(u3) };
            #pragma unroll
            for (int c = 0; c < 4; c++) {
                int co = co0 + c;
                g_out1p[(s*CO1 + co)*P1LEN + p] = A*r[c] + Cf*g_wsum1[co] + b1[co];
            }
        }
    }

    grid_barrier(&g_barB);

    // =====================================================================
    // Phase 3 (blocks 0..127): avgpool2 -> conv2(1x1) -> conv3 -> proj ->
    // argmax. Block handles s = bx>>1, channel half ch = bx&1 (16 channels).
    // =====================================================================
    if (bx >= 2*SS) return;
    {
        int s  = bx >> 1;
        int ch = bx & 1;
        float* o1  = smf;              // 1824
        float* wls = smf + 1824;       // 4608
        float* bls = smf + 6432;       // 128
        float* o2  = smf + 6560;       // 304
        float* o3  = smf + 6864;       // 576 (local 16 channels)

        for (int i = tid; i < CO1*P1LEN; i += NTHR) o1[i] = g_out1p[s*CO1*P1LEN + i];
        for (int i = tid; i < NV*T3;    i += NTHR) wls[i] = wl[i];
        if (tid < NV) bls[tid] = bl[tid];
        __syncthreads();

        // avgpool(3) then conv2 1x1 (commutes with reference conv2->pool)
        for (int i = tid; i < CO2*P2LEN; i += NTHR) {
            int c8 = i / P2LEN;
            int q  = i - c8*P2LEN;
            float acc = 0.f;
            #pragma unroll
            for (int ci = 0; ci < CO1; ci++) {
                const float* r = o1 + ci*P1LEN + 3*q;
                acc += w2[c8*CO1 + ci] * (r[0] + r[1] + r[2]);
            }
            o2[i] = acc * (1.f/3.f) + b2[c8];
        }
        __syncthreads();

        // conv3 for this half's 16 channels
        for (int i = tid; i < 16*T3; i += NTHR) {
            int col = i / T3;          // local channel 0..15
            int co  = ch*16 + col;
            int t   = i - col*T3;
            float acc = b3[co];
            #pragma unroll
            for (int c8 = 0; c8 < CO2; c8++) {
                const float* r = o2 + c8*P2LEN + t;
                const float* w = w3 + (co*CO2 + c8)*3;
                acc += w[0]*r[0] + w[1]*r[1] + w[2]*r[2];
            }
            o3[col*T3 + t] = acc;
        }
        __syncthreads();

        // projection to 128 vocab + argmax (first-max semantics like jnp.argmax)
        int cl = tid >> 3;   // local channel 0..15
        int vl = tid & 7;    // vocab lane
        float orow[T3];
        #pragma unroll
        for (int k = 0; k < T3; k++) orow[k] = o3[cl*T3 + k];

        float bestv = -3.4e38f;
        int   besti = 0;
        #pragma unroll 2
        for (int i = 0; i < 16; i++) {
            int v = vl + 8*i;
            float d = bls[v];
            const float* wr = wls + v*T3;
            #pragma unroll
            for (int k = 0; k < T3; k++) d += orow[k] * wr[k];
            if (d > bestv) { bestv = d; besti = v; }  // strict > keeps first max
        }
        #pragma unroll
        for (int off = 4; off >= 1; off >>= 1) {
            float ov = __shfl_down_sync(0xffffffffu, bestv, off);
            int   oi = __shfl_down_sync(0xffffffffu, besti, off);
            if (ov > bestv || (ov == bestv && oi < besti)) { bestv = ov; besti = oi; }
        }
        if (vl == 0) out[s*BB + ch*16 + cl] = (float)besti;
    }
}

// ---------------------------------------------------------------------------
extern "C" void kernel_launch(void* const* d_in, const int* in_sizes, int n_in,
                              void* d_out, int out_size) {
    const int*   tokens = (const int*)  d_in[0];
    const float* emb    = (const float*)d_in[1];
    const float* pos    = (const float*)d_in[2];
    const float* gamma  = (const float*)d_in[3];
    const float* beta   = (const float*)d_in[4];
    const float* w1     = (const float*)d_in[5];
    const float* b1     = (const float*)d_in[6];
    const float* w2     = (const float*)d_in[7];
    const float* b2     = (const float*)d_in[8];
    const float* w3     = (const float*)d_in[9];
    const float* b3     = (const float*)d_in[10];
    const float* wl     = (const float*)d_in[11];
    const float* bl     = (const float*)d_in[12];
    float* out = (float*)d_out;

    size_t sh = (size_t)(BB*XSTR + BB*KP*16) * sizeof(float);  // 66048 B
    cudaFuncSetAttribute(kF, cudaFuncAttributeMaxDynamicSharedMemorySize, (int)sh);

    kF<<<NBLK, NTHR, sh>>>(tokens, emb, pos, gamma, beta, w1, b1,
                           w2, b2, w3, b3, wl, bl, out);
}

// round 6
// speedup vs baseline: 1.0960x; 1.0960x over previous
#include <cuda_runtime.h>
#include <math.h>

// Problem constants
#define SS 64
#define BB 32
#define DM 586
#define DE 583
#define NL 4
#define K1 17
#define CO1 16
#define P1LEN 114
#define KP 21       // combined conv1+pool kernel length
#define CO2 8
#define P2LEN 38
#define CO3 32
#define T3 36
#define NV 128
#define XSTR 304    // smem x row stride in kC (301 valid + pad)

// Scratch (no allocations allowed)
__device__ float g_x0[SS*BB*DM];
__device__ float g_part[SS*2*2];                    // per (s, half): {sum, sumsq}
__device__ __align__(16) float g_w1ps[BB*KP*16];    // [ci*21+m][16 co]
__device__ float g_wsum1[CO1];
__device__ float g_out1p[SS*CO1*P1LEN];

// ---------------------------------------------------------------------------
// Kernel S (blocks 0..127): embedding gather (*sqrt(D)) + pos -> g_x0, and
// partial per-s sums. Block bx handles s = bx>>1, rows [16*(bx&1), +16).
// 1024 threads = 32 warps; 2 warps per row, each striding 64.
// Kernel S (blocks 128..143): combined conv1+pool weights for co = bx-128
// and wsum1[co] = sum of raw w1[co] (pooling coverage identity).
// ---------------------------------------------------------------------------
__global__ void __launch_bounds__(1024)
kS(const int* __restrict__ tokens, const float* __restrict__ emb,
   const float* __restrict__ pos, const float* __restrict__ w1) {
    int tid  = threadIdx.x;
    int wid  = tid >> 5;
    int lane = tid & 31;

    if (blockIdx.x < 2*SS) {
        int s    = blockIdx.x >> 1;
        int half = blockIdx.x & 1;
        const float scale = sqrtf(586.0f);
        int b    = half*16 + (wid >> 1);   // row within batch
        int part = wid & 1;                // which half of the row this warp covers
        int tok  = tokens[s*BB + b];
        const float* row = emb + (size_t)tok * DE;
        float* xrow = g_x0 + (size_t)(s*BB + b) * DM;
        float sum = 0.f, sq = 0.f;
        int d = lane + 32*part;
        #pragma unroll 3
        for (; d < DE; d += 64) {
            float v = row[d] * scale;
            xrow[d] = v;
            sum += v; sq += v*v;
        }
        if (part == 0 && lane < 3) {
            float v = pos[(s*BB + b)*3 + lane];
            xrow[DE + lane] = v;
            sum += v; sq += v*v;
        }
        #pragma unroll
        for (int off = 16; off >= 1; off >>= 1) {
            sum += __shfl_down_sync(0xffffffffu, sum, off);
            sq  += __shfl_down_sync(0xffffffffu, sq,  off);
        }
        __shared__ float shs[64];
        if (lane == 0) { shs[wid] = sum; shs[32 + wid] = sq; }
        __syncthreads();
        if (wid == 0) {
            float a = shs[lane];
            float c = shs[32 + lane];
            #pragma unroll
            for (int off = 16; off >= 1; off >>= 1) {
                a += __shfl_down_sync(0xffffffffu, a, off);
                c += __shfl_down_sync(0xffffffffu, c, off);
            }
            if (lane == 0) {
                g_part[(s*2 + half)*2 + 0] = a;
                g_part[(s*2 + half)*2 + 1] = c;
            }
        }
    } else {
        // weight prep for one output channel
        int co = blockIdx.x - 2*SS;
        const float* wrow = w1 + co*BB*K1;   // 544 floats
        // combined weights: w1p[ci][m] = 0.2 * sum_j w1[ci][m-j], j in [max(0,m-16), min(4,m)]
        if (tid < BB*KP) {
            int ci = tid / KP;
            int m  = tid - ci*KP;
            int jlo = m - (K1-1); if (jlo < 0) jlo = 0;
            int jhi = m;          if (jhi > 4) jhi = 4;
            float acc = 0.f;
            for (int j = jlo; j <= jhi; j++)
                acc += wrow[ci*K1 + (m - j)];
            g_w1ps[tid*16 + co] = acc * 0.2f;
        }
        // wsum1[co] = sum of all 544 raw weights (each tap covered 5x * 1/5)
        float p = (tid < BB*K1) ? wrow[tid] : 0.f;
        #pragma unroll
        for (int off = 16; off >= 1; off >>= 1)
            p += __shfl_down_sync(0xffffffffu, p, off);
        __shared__ float shw[32];
        if (lane == 0) shw[wid] = p;
        __syncthreads();
        if (wid == 0) {
            float q = shw[lane];
            #pragma unroll
            for (int off = 16; off >= 1; off >>= 1)
                q += __shfl_down_sync(0xffffffffu, q, off);
            if (lane == 0) g_wsum1[co] = q;
        }
    }
}

// ---------------------------------------------------------------------------
// Kernel C: fused conv1+avgpool1 as a stride-5, K=21 conv on g_x0.
// grid = 128 (64 s x 2 p-halves of 57), block = 128.
// Tile: 8 co x 1 p per thread; f32x2 packed FMA, weights via 2x LDS.128/tap.
// BN affine computed inline from g_part + gamma/beta, folded into epilogue.
// ---------------------------------------------------------------------------
__global__ void __launch_bounds__(128)
kC(const float* __restrict__ gamma, const float* __restrict__ beta,
   const float* __restrict__ b1) {
    int bx = blockIdx.x;
    int s  = bx >> 1;
    int hh = bx & 1;
    int p0 = hh * 57;
    int CH = 57;                // both halves: 57 (114 total)
    int d0 = p0 * 5;
    int span = (CH-1)*5 + KP;   // 301

    extern __shared__ float sm[];
    float* xs = sm;                    // BB * XSTR = 9728 floats
    float* ws = sm + BB*XSTR;          // 672 * 16  = 10752 floats

    int tid = threadIdx.x;
    // Load x slice (301 valid cols per ci, zero-padded to XSTR)
    for (int idx = tid; idx < BB*XSTR; idx += 128) {
        int ci = idx >> 8;             // not exact: XSTR=304, use div
        ci = idx / XSTR;
        int dd = idx - ci*XSTR;
        float v = 0.f;
        if (dd < span) v = g_x0[(s*BB + ci)*DM + d0 + dd];
        xs[idx] = v;
    }
    // Load combined weights (vectorized)
    {
        const float4* wsrc = (const float4*)g_w1ps;
        float4* wdst = (float4*)ws;
        for (int idx = tid; idx < BB*KP*4; idx += 128) wdst[idx] = wsrc[idx];
    }
    __syncthreads();

    int pt  = tid >> 1;   // 0..63 (p position within half; 57..63 inactive at epilogue)
    int cop = tid & 1;    // 0..1 -> co group of 8
    int co0 = cop * 8;
    unsigned long long acc0 = 0ull, acc1 = 0ull, acc2 = 0ull, acc3 = 0ull;
    const float* xr0 = xs + 5*pt;
    const float* wp0 = ws + co0;
    #pragma unroll 2
    for (int ci = 0; ci < BB; ci++) {
        const float* xr = xr0 + ci*XSTR;
        const float* wp = wp0 + ci*(KP*16);
        #pragma unroll
        for (int m = 0; m < KP; m++) {
            float xv = xr[m];
            unsigned long long xd;
            asm("mov.b64 %0, {%1, %1};" : "=l"(xd) : "r"(__float_as_uint(xv)));
            ulonglong2 wa = *(const ulonglong2*)(wp + m*16);
            ulonglong2 wb = *(const ulonglong2*)(wp + m*16 + 4);
            asm("fma.rn.f32x2 %0, %1, %2, %3;" : "=l"(acc0) : "l"(wa.x), "l"(xd), "l"(acc0));
            asm("fma.rn.f32x2 %0, %1, %2, %3;" : "=l"(acc1) : "l"(wa.y), "l"(xd), "l"(acc1));
            asm("fma.rn.f32x2 %0, %1, %2, %3;" : "=l"(acc2) : "l"(wb.x), "l"(xd), "l"(acc2));
            asm("fma.rn.f32x2 %0, %1, %2, %3;" : "=l"(acc3) : "l"(wb.y), "l"(xd), "l"(acc3));
        }
    }
    // BN affine fold (redundant per thread; broadcast loads)
    float A, Cf;
    {
        float invN = 1.f / (float)(BB*DM);
        float ts = g_part[s*4 + 0] + g_part[s*4 + 2];
        float tq = g_part[s*4 + 1] + g_part[s*4 + 3];
        float m = ts * invN;
        float v = tq * invN - m*m;   // biased var, matches reference
        A = 1.f; Cf = 0.f;
        #pragma unroll
        for (int l = 0; l < NL; l++) {
            float g  = gamma[l*SS + s];
            float bb = beta[l*SS + s];
            float inv = rsqrtf(v + 1e-5f);
            float a = g * inv;
            float c = bb - a * m;
            A = a * A;
            Cf = a * Cf + c;
            m = bb;
            v = a * a * v;
        }
    }
    if (pt < CH) {
        int p = p0 + pt;
        unsigned u[8];
        asm("mov.b64 {%0, %1}, %2;" : "=r"(u[0]), "=r"(u[1]) : "l"(acc0));
        asm("mov.b64 {%0, %1}, %2;" : "=r"(u[2]), "=r"(u[3]) : "l"(acc1));
        asm("mov.b64 {%0, %1}, %2;" : "=r"(u[4]), "=r"(u[5]) : "l"(acc2));
        asm("mov.b64 {%0, %1}, %2;" : "=r"(u[6]), "=r"(u[7]) : "l"(acc3));
        #pragma unroll
        for (int c = 0; c < 8; c++) {
            int co = co0 + c;
            g_out1p[(s*CO1 + co)*P1LEN + p] =
                A*__uint_as_float(u[c]) + Cf*g_wsum1[co] + b1[co];
        }
    }
}

// ---------------------------------------------------------------------------
// Kernel D: avgpool2 -> conv2(1x1) -> conv3(K=3) -> proj(128x36) -> argmax.
// grid = 64 (one per s), block = 256.
// ---------------------------------------------------------------------------
__global__ void kD(const float* __restrict__ w2, const float* __restrict__ b2,
                   const float* __restrict__ w3, const float* __restrict__ b3,
                   const float* __restrict__ wl, const float* __restrict__ bl,
                   float* __restrict__ out) {
    int s = blockIdx.x;
    int tid = threadIdx.x;
    __shared__ float o1[CO1*P1LEN];
    __shared__ float wls[NV*T3];
    __shared__ float bls[NV];
    __shared__ float o2[CO2*P2LEN];
    __shared__ float o3[CO3*T3];

    for (int i = tid; i < CO1*P1LEN; i += 256) o1[i] = g_out1p[s*CO1*P1LEN + i];
    for (int i = tid; i < NV*T3;    i += 256) wls[i] = wl[i];
    if (tid < NV) bls[tid] = bl[tid];
    __syncthreads();

    // avgpool(3) then conv2 1x1 (commutes with reference conv2->pool)
    for (int i = tid; i < CO2*P2LEN; i += 256) {
        int c8 = i / P2LEN;
        int q  = i - c8*P2LEN;
        float acc = 0.f;
        #pragma unroll
        for (int ci = 0; ci < CO1; ci++) {
            const float* r = o1 + ci*P1LEN + 3*q;
            acc += w2[c8*CO1 + ci] * (r[0] + r[1] + r[2]);
        }
        o2[i] = acc * (1.f/3.f) + b2[c8];
    }
    __syncthreads();

    // conv3: (8,38) -> (32,36), K=3
    for (int i = tid; i < CO3*T3; i += 256) {
        int co = i / T3;
        int t  = i - co*T3;
        float acc = b3[co];
        #pragma unroll
        for (int c8 = 0; c8 < CO2; c8++) {
            const float* r = o2 + c8*P2LEN + t;
            const float* w = w3 + (co*CO2 + c8)*3;
            acc += w[0]*r[0] + w[1]*r[1] + w[2]*r[2];
        }
        o3[i] = acc;
    }
    __syncthreads();

    // projection to 128 vocab + argmax (first-max semantics like jnp.argmax)
    int c  = tid >> 3;
    int vl = tid & 7;
    float orow[T3];
    #pragma unroll
    for (int k = 0; k < T3; k++) orow[k] = o3[c*T3 + k];

    float bestv = -3.4e38f;
    int   besti = 0;
    #pragma unroll 2
    for (int i = 0; i < 16; i++) {
        int v = vl + 8*i;
        float d = bls[v];
        const float* wr = wls + v*T3;
        #pragma unroll
        for (int k = 0; k < T3; k++) d += orow[k] * wr[k];
        if (d > bestv) { bestv = d; besti = v; }  // strict > keeps first max within lane
    }
    #pragma unroll
    for (int off = 4; off >= 1; off >>= 1) {
        float ov = __shfl_down_sync(0xffffffffu, bestv, off);
        int   oi = __shfl_down_sync(0xffffffffu, besti, off);
        if (ov > bestv || (ov == bestv && oi < besti)) { bestv = ov; besti = oi; }
    }
    if (vl == 0) out[s*BB + c] = (float)besti;
}

// ---------------------------------------------------------------------------
extern "C" void kernel_launch(void* const* d_in, const int* in_sizes, int n_in,
                              void* d_out, int out_size) {
    const int*   tokens = (const int*)  d_in[0];
    const float* emb    = (const float*)d_in[1];
    const float* pos    = (const float*)d_in[2];
    const float* gamma  = (const float*)d_in[3];
    const float* beta   = (const float*)d_in[4];
    const float* w1     = (const float*)d_in[5];
    const float* b1     = (const float*)d_in[6];
    const float* w2     = (const float*)d_in[7];
    const float* b2     = (const float*)d_in[8];
    const float* w3     = (const float*)d_in[9];
    const float* b3     = (const float*)d_in[10];
    const float* wl     = (const float*)d_in[11];
    const float* bl     = (const float*)d_in[12];
    float* out = (float*)d_out;

    size_t shC = (size_t)(BB*XSTR + BB*KP*16) * sizeof(float);  // 81920 B
    cudaFuncSetAttribute(kC, cudaFuncAttributeMaxDynamicSharedMemorySize, (int)shC);

    kS<<<2*SS + CO1, 1024>>>(tokens, emb, pos, w1);
    kC<<<128, 128, shC>>>(gamma, beta, b1);
    kD<<<SS, 256>>>(w2, b2, w3, b3, wl, bl, out);
}

// round 7
// speedup vs baseline: 1.0969x; 1.0008x over previous
#include <cuda_runtime.h>
#include <math.h>

// Problem constants
#define SS 64
#define BB 32
#define DM 586
#define DE 583
#define NL 4
#define K1 17
#define CO1 16
#define P1LEN 114
#define KP 21       // combined conv1+pool kernel length
#define CO2 8
#define P2LEN 38
#define CO3 32
#define T3 36
#define NV 128
#define XSTR 168    // smem x row stride in conv phase (<=161 valid + pad)

// Scratch (no allocations allowed)
__device__ float g_x0[SS*BB*DM];
__device__ float g_part[SS*2*2];                    // per (s, half): {sum, sumsq}
__device__ __align__(16) float g_w1ps[BB*KP*16];    // [ci*21+m][16 co]
__device__ float g_wsum1[CO1];
__device__ float g_out1p[SS*CO1*P1LEN];
__device__ unsigned g_scnt[SS];                     // per-s arrival counters (monotonic)

// ---------------------------------------------------------------------------
// Kernel S (blocks 0..127): embedding gather (*sqrt(D)) + pos -> g_x0, and
// partial per-s sums. Block bx handles s = bx>>1, rows [16*(bx&1), +16).
// 1024 threads = 32 warps; 2 warps per row, each striding 64, fully unrolled
// (10 predicated LDGs in flight per warp -> high MLP on the random gather).
// Kernel S (blocks 128..143): combined conv1+pool weights for co = bx-128
// and wsum1[co] = sum of raw w1[co] (pooling coverage identity).
// ---------------------------------------------------------------------------
__global__ void __launch_bounds__(1024)
kS(const int* __restrict__ tokens, const float* __restrict__ emb,
   const float* __restrict__ pos, const float* __restrict__ w1) {
    int tid  = threadIdx.x;
    int wid  = tid >> 5;
    int lane = tid & 31;

    if (blockIdx.x < 2*SS) {
        int s    = blockIdx.x >> 1;
        int half = blockIdx.x & 1;
        const float scale = sqrtf(586.0f);
        int b    = half*16 + (wid >> 1);   // row within batch
        int part = wid & 1;                // which half of the row this warp covers
        int tok  = tokens[s*BB + b];
        const float* row = emb + (size_t)tok * DE;
        float* xrow = g_x0 + (size_t)(s*BB + b) * DM;
        float sum = 0.f, sq = 0.f;
        int dbase = lane + 32*part;
        #pragma unroll
        for (int k = 0; k < 10; k++) {
            int d = dbase + 64*k;
            if (d < DE) {
                float v = row[d] * scale;
                xrow[d] = v;
                sum += v; sq += v*v;
            }
        }
        if (part == 0 && lane < 3) {
            float v = pos[(s*BB + b)*3 + lane];
            xrow[DE + lane] = v;
            sum += v; sq += v*v;
        }
        #pragma unroll
        for (int off = 16; off >= 1; off >>= 1) {
            sum += __shfl_down_sync(0xffffffffu, sum, off);
            sq  += __shfl_down_sync(0xffffffffu, sq,  off);
        }
        __shared__ float shs[64];
        if (lane == 0) { shs[wid] = sum; shs[32 + wid] = sq; }
        __syncthreads();
        if (wid == 0) {
            float a = shs[lane];
            float c = shs[32 + lane];
            #pragma unroll
            for (int off = 16; off >= 1; off >>= 1) {
                a += __shfl_down_sync(0xffffffffu, a, off);
                c += __shfl_down_sync(0xffffffffu, c, off);
            }
            if (lane == 0) {
                g_part[(s*2 + half)*2 + 0] = a;
                g_part[(s*2 + half)*2 + 1] = c;
            }
        }
    } else {
        // weight prep for one output channel
        int co = blockIdx.x - 2*SS;
        const float* wrow = w1 + co*BB*K1;   // 544 floats
        // combined: w1p[ci][m] = 0.2 * sum_j w1[ci][m-j], j in [max(0,m-16), min(4,m)]
        if (tid < BB*KP) {
            int ci = tid / KP;
            int m  = tid - ci*KP;
            int jlo = m - (K1-1); if (jlo < 0) jlo = 0;
            int jhi = m;          if (jhi > 4) jhi = 4;
            float acc = 0.f;
            for (int j = jlo; j <= jhi; j++)
                acc += wrow[ci*K1 + (m - j)];
            g_w1ps[tid*16 + co] = acc * 0.2f;
        }
        // wsum1[co] = sum of all 544 raw weights
        float p = (tid < BB*K1) ? wrow[tid] : 0.f;
        #pragma unroll
        for (int off = 16; off >= 1; off >>= 1)
            p += __shfl_down_sync(0xffffffffu, p, off);
        __shared__ float shw[32];
        if (lane == 0) shw[wid] = p;
        __syncthreads();
        if (wid == 0) {
            float q = shw[lane];
            #pragma unroll
            for (int off = 16; off >= 1; off >>= 1)
                q += __shfl_down_sync(0xffffffffu, q, off);
            if (lane == 0) g_wsum1[co] = q;
        }
    }
}

// ---------------------------------------------------------------------------
// Kernel CD: fused conv1+avgpool1 (stride-5 K=21 conv on g_x0) + per-s tail
// (avgpool2, conv2, conv3, projection, argmax) run by the LAST arriving of
// the 4 chunk-blocks of each s (per-s monotonic counter; deterministic).
// grid = 256 (64 s x 4 p-chunks of {29,29,28,28}), block = 128, ~64.5KB smem
// -> 3 blocks/SM. Conv tile: 2 co x 2 p per thread with f32x2 packed FMA.
// ---------------------------------------------------------------------------
__global__ void __launch_bounds__(128)
kCD(const float* __restrict__ gamma, const float* __restrict__ beta,
    const float* __restrict__ b1,
    const float* __restrict__ w2, const float* __restrict__ b2,
    const float* __restrict__ w3, const float* __restrict__ b3,
    const float* __restrict__ wl, const float* __restrict__ bl,
    float* __restrict__ out) {
    extern __shared__ float smf[];
    int bx  = blockIdx.x;
    int tid = threadIdx.x;
    int s   = bx >> 2;
    int cc  = bx & 3;
    int p0  = (cc < 2) ? cc*29 : 58 + (cc-2)*28;
    int CH  = (cc < 2) ? 29 : 28;
    int d0  = p0 * 5;
    int span = (CH-1)*5 + KP;  // 161 or 156

    // ===================== conv phase =====================
    {
        float* xs = smf;                    // BB*XSTR = 5376 floats
        float* ws = smf + BB*XSTR;          // 672*16  = 10752 floats

        for (int idx = tid; idx < BB*XSTR; idx += 128) {
            int ci = idx / XSTR;
            int dd = idx - ci*XSTR;
            float v = 0.f;
            if (dd < span) v = g_x0[(s*BB + ci)*DM + d0 + dd];
            xs[idx] = v;
        }
        {
            const float4* wsrc = (const float4*)g_w1ps;
            float4* wdst = (float4*)ws;
            for (int idx = tid; idx < BB*KP*4; idx += 128) wdst[idx] = wsrc[idx];
        }
        __syncthreads();

        int pt  = tid >> 3;   // 0..15 -> p pair base
        int cop = tid & 7;    // 0..7 co-pairs
        int pl0 = pt * 2;
        int co0 = cop * 2;
        unsigned long long accp0 = 0ull, accp1 = 0ull;  // (co0,co0+1) at p0/p1
        const float* xbase = xs + 5*pl0;
        #pragma unroll 2
        for (int ci = 0; ci < BB; ci++) {
            const float* xr = xbase + ci*XSTR;
            float xw[26];
            #pragma unroll
            for (int i = 0; i < 26; i++) xw[i] = xr[i];
            const float* wp = ws + ci*(KP*16) + co0;
            #pragma unroll
            for (int m = 0; m < KP; m++) {
                unsigned long long wv = *(const unsigned long long*)(wp + m*16);
                unsigned long long xd0, xd1;
                asm("mov.b64 %0, {%1, %1};" : "=l"(xd0) : "r"(__float_as_uint(xw[m])));
                asm("mov.b64 %0, {%1, %1};" : "=l"(xd1) : "r"(__float_as_uint(xw[m+5])));
                asm("fma.rn.f32x2 %0, %1, %2, %3;" : "=l"(accp0) : "l"(wv), "l"(xd0), "l"(accp0));
                asm("fma.rn.f32x2 %0, %1, %2, %3;" : "=l"(accp1) : "l"(wv), "l"(xd1), "l"(accp1));
            }
        }
        // BN affine fold (redundant per thread; broadcast loads)
        float A, Cf;
        {
            float invN = 1.f / (float)(BB*DM);
            float ts = g_part[s*4 + 0] + g_part[s*4 + 2];
            float tq = g_part[s*4 + 1] + g_part[s*4 + 3];
            float m = ts * invN;
            float v = tq * invN - m*m;   // biased var, matches reference
            A = 1.f; Cf = 0.f;
            #pragma unroll
            for (int l = 0; l < NL; l++) {
                float g  = gamma[l*SS + s];
                float bb = beta[l*SS + s];
                float inv = rsqrtf(v + 1e-5f);
                float a = g * inv;
                float c = bb - a * m;
                A = a * A;
                Cf = a * Cf + c;
                m = bb;
                v = a * a * v;
            }
        }
        unsigned u00, u01, u10, u11;
        asm("mov.b64 {%0, %1}, %2;" : "=r"(u00), "=r"(u01) : "l"(accp0));
        asm("mov.b64 {%0, %1}, %2;" : "=r"(u10), "=r"(u11) : "l"(accp1));
        float bias0 = Cf * g_wsum1[co0]   + b1[co0];
        float bias1 = Cf * g_wsum1[co0+1] + b1[co0+1];
        if (pl0 < CH) {
            int p = p0 + pl0;
            g_out1p[(s*CO1 + co0  )*P1LEN + p] = A*__uint_as_float(u00) + bias0;
            g_out1p[(s*CO1 + co0+1)*P1LEN + p] = A*__uint_as_float(u01) + bias1;
        }
        if (pl0 + 1 < CH) {
            int p = p0 + pl0 + 1;
            g_out1p[(s*CO1 + co0  )*P1LEN + p] = A*__uint_as_float(u10) + bias0;
            g_out1p[(s*CO1 + co0+1)*P1LEN + p] = A*__uint_as_float(u11) + bias1;
        }
    }

    // ===================== arrival: last of 4 blocks per s runs the tail ====
    __threadfence();          // release our g_out1p writes
    __syncthreads();
    __shared__ int sh_last;
    if (tid == 0) {
        unsigned old = atomicAdd(&g_scnt[s], 1u);
        sh_last = ((old & 3u) == 3u) ? 1 : 0;
        __threadfence();      // acquire
    }
    __syncthreads();
    if (!sh_last) return;

    // ===================== tail phase (one block per s) =====================
    {
        float* o1  = smf;              // 1824
        float* wls = smf + 1824;       // 4608 (16B-aligned: 1824*4=7296)
        float* bls = smf + 6432;       // 128
        float* o2  = smf + 6560;       // 304
        float* o3  = smf + 6864;       // 1152

        for (int i = tid; i < CO1*P1LEN; i += 128)
            o1[i] = __ldcg(&g_out1p[s*CO1*P1LEN + i]);   // bypass L1: remote writes
        for (int i = tid; i < NV*T3; i += 128) wls[i] = wl[i];
        if (tid < NV) bls[tid] = bl[tid];
        __syncthreads();

        // avgpool(3) then conv2 1x1 (commutes with reference conv2->pool)
        for (int i = tid; i < CO2*P2LEN; i += 128) {
            int c8 = i / P2LEN;
            int q  = i - c8*P2LEN;
            float acc = 0.f;
            #pragma unroll
            for (int ci = 0; ci < CO1; ci++) {
                const float* r = o1 + ci*P1LEN + 3*q;
                acc += w2[c8*CO1 + ci] * (r[0] + r[1] + r[2]);
            }
            o2[i] = acc * (1.f/3.f) + b2[c8];
        }
        __syncthreads();

        // conv3: (8,38) -> (32,36), K=3
        for (int i = tid; i < CO3*T3; i += 128) {
            int co = i / T3;
            int t  = i - co*T3;
            float acc = b3[co];
            #pragma unroll
            for (int c8 = 0; c8 < CO2; c8++) {
                const float* r = o2 + c8*P2LEN + t;
                const float* w = w3 + (co*CO2 + c8)*3;
                acc += w[0]*r[0] + w[1]*r[1] + w[2]*r[2];
            }
            o3[i] = acc;
        }
        __syncthreads();

        // projection to 128 vocab + argmax (first-max semantics like jnp.argmax)
        int c  = tid >> 2;   // channel 0..31
        int vl = tid & 3;    // vocab lane
        float orow[T3];
        #pragma unroll
        for (int k = 0; k < T3; k++) orow[k] = o3[c*T3 + k];

        float bestv = -3.4e38f;
        int   besti = 0;
        for (int i = 0; i < 32; i++) {
            int v = vl + 4*i;
            float d = bls[v];
            const float4* wr = (const float4*)(wls + v*T3);  // 36 floats = 9 float4
            #pragma unroll
            for (int k4 = 0; k4 < 9; k4++) {
                float4 w4 = wr[k4];
                d += orow[4*k4+0]*w4.x + orow[4*k4+1]*w4.y
                   + orow[4*k4+2]*w4.z + orow[4*k4+3]*w4.w;
            }
            if (d > bestv) { bestv = d; besti = v; }  // strict > keeps first max in lane
        }
        #pragma unroll
        for (int off = 2; off >= 1; off >>= 1) {
            float ov = __shfl_down_sync(0xffffffffu, bestv, off);
            int   oi = __shfl_down_sync(0xffffffffu, besti, off);
            if (ov > bestv || (ov == bestv && oi < besti)) { bestv = ov; besti = oi; }
        }
        if (vl == 0) out[s*BB + c] = (float)besti;
    }
}

// ---------------------------------------------------------------------------
extern "C" void kernel_launch(void* const* d_in, const int* in_sizes, int n_in,
                              void* d_out, int out_size) {
    const int*   tokens = (const int*)  d_in[0];
    const float* emb    = (const float*)d_in[1];
    const float* pos    = (const float*)d_in[2];
    const float* gamma  = (const float*)d_in[3];
    const float* beta   = (const float*)d_in[4];
    const float* w1     = (const float*)d_in[5];
    const float* b1     = (const float*)d_in[6];
    const float* w2     = (const float*)d_in[7];
    const float* b2     = (const float*)d_in[8];
    const float* w3     = (const float*)d_in[9];
    const float* b3     = (const float*)d_in[10];
    const float* wl     = (const float*)d_in[11];
    const float* bl     = (const float*)d_in[12];
    float* out = (float*)d_out;

    size_t sh = (size_t)(BB*XSTR + BB*KP*16) * sizeof(float);  // 64512 B
    cudaFuncSetAttribute(kCD, cudaFuncAttributeMaxDynamicSharedMemorySize, (int)sh);

    kS<<<2*SS + CO1, 1024>>>(tokens, emb, pos, w1);
    kCD<<<256, 128, sh>>>(gamma, beta, b1, w2, b2, w3, b3, wl, bl, out);
}

// round 8
// speedup vs baseline: 1.3811x; 1.2591x over previous
#include <cuda_runtime.h>
#include <math.h>

// Problem constants
#define SS 64
#define BB 32
#define DM 586
#define DE 583
#define NL 4
#define K1 17
#define CO1 16
#define P1LEN 114
#define KP 21       // combined conv1+pool kernel length
#define CO2 8
#define P2LEN 38
#define CO3 32
#define T3 36
#define NV 128
#define XSTR 168    // smem x row stride in kC (<=161 valid + pad)
#define NCG 4       // ci groups
#define CIG 8       // ci per group

// Scratch (no allocations allowed)
__device__ float g_x0[SS*BB*DM];
__device__ float g_part[SS*2*2];                    // per (s, half): {sum, sumsq}
__device__ __align__(16) float g_w1ps[BB*KP*16];    // [ci*21+m][16 co]
__device__ float g_wsum1[CO1];
__device__ float g_c1part[NCG*SS*CO1*P1LEN];        // raw conv partials per ci-group

// ---------------------------------------------------------------------------
// Kernel S (blocks 0..127): embedding gather (*sqrt(D)) + pos -> g_x0, and
// partial per-s sums. Block bx handles s = bx>>1, rows [16*(bx&1), +16).
// 1024 threads = 32 warps; 2 warps per row, fully unrolled (10 predicated
// LDGs in flight per warp -> high MLP on the random gather).
// Kernel S (blocks 128..143): combined conv1+pool weights for co = bx-128
// and wsum1[co] = sum of raw w1[co] (pooling coverage identity).
// ---------------------------------------------------------------------------
__global__ void __launch_bounds__(1024)
kS(const int* __restrict__ tokens, const float* __restrict__ emb,
   const float* __restrict__ pos, const float* __restrict__ w1) {
    int tid  = threadIdx.x;
    int wid  = tid >> 5;
    int lane = tid & 31;

    if (blockIdx.x < 2*SS) {
        int s    = blockIdx.x >> 1;
        int half = blockIdx.x & 1;
        const float scale = sqrtf(586.0f);
        int b    = half*16 + (wid >> 1);   // row within batch
        int part = wid & 1;                // which half of the row this warp covers
        int tok  = tokens[s*BB + b];
        const float* row = emb + (size_t)tok * DE;
        float* xrow = g_x0 + (size_t)(s*BB + b) * DM;
        float sum = 0.f, sq = 0.f;
        int dbase = lane + 32*part;
        #pragma unroll
        for (int k = 0; k < 10; k++) {
            int d = dbase + 64*k;
            if (d < DE) {
                float v = row[d] * scale;
                xrow[d] = v;
                sum += v; sq += v*v;
            }
        }
        if (part == 0 && lane < 3) {
            float v = pos[(s*BB + b)*3 + lane];
            xrow[DE + lane] = v;
            sum += v; sq += v*v;
        }
        #pragma unroll
        for (int off = 16; off >= 1; off >>= 1) {
            sum += __shfl_down_sync(0xffffffffu, sum, off);
            sq  += __shfl_down_sync(0xffffffffu, sq,  off);
        }
        __shared__ float shs[64];
        if (lane == 0) { shs[wid] = sum; shs[32 + wid] = sq; }
        __syncthreads();
        if (wid == 0) {
            float a = shs[lane];
            float c = shs[32 + lane];
            #pragma unroll
            for (int off = 16; off >= 1; off >>= 1) {
                a += __shfl_down_sync(0xffffffffu, a, off);
                c += __shfl_down_sync(0xffffffffu, c, off);
            }
            if (lane == 0) {
                g_part[(s*2 + half)*2 + 0] = a;
                g_part[(s*2 + half)*2 + 1] = c;
            }
        }
    } else {
        // weight prep for one output channel
        int co = blockIdx.x - 2*SS;
        const float* wrow = w1 + co*BB*K1;   // 544 floats
        // combined: w1p[ci][m] = 0.2 * sum_j w1[ci][m-j], j in [max(0,m-16), min(4,m)]
        if (tid < BB*KP) {
            int ci = tid / KP;
            int m  = tid - ci*KP;
            int jlo = m - (K1-1); if (jlo < 0) jlo = 0;
            int jhi = m;          if (jhi > 4) jhi = 4;
            float acc = 0.f;
            for (int j = jlo; j <= jhi; j++)
                acc += wrow[ci*K1 + (m - j)];
            g_w1ps[tid*16 + co] = acc * 0.2f;
        }
        // wsum1[co] = sum of all 544 raw weights
        float p = (tid < BB*K1) ? wrow[tid] : 0.f;
        #pragma unroll
        for (int off = 16; off >= 1; off >>= 1)
            p += __shfl_down_sync(0xffffffffu, p, off);
        __shared__ float shw[32];
        if (lane == 0) shw[wid] = p;
        __syncthreads();
        if (wid == 0) {
            float q = shw[lane];
            #pragma unroll
            for (int off = 16; off >= 1; off >>= 1)
                q += __shfl_down_sync(0xffffffffu, q, off);
            if (lane == 0) g_wsum1[co] = q;
        }
    }
}

// ---------------------------------------------------------------------------
// Kernel C: fused conv1+avgpool1 (stride-5, K=21) on g_x0, PARTIAL over a
// group of 8 ci. grid = 1024 (64 s x 4 p-chunks x 4 ci-groups), block = 128.
// 16KB static smem -> ~7 blocks/SM resident -> ~27 warps/SM (latency hidden).
// Tile: 2 co x 2 p per thread (4 independent FMA chains). Raw partial sums
// only; BN affine + bias applied later in kD.
// ---------------------------------------------------------------------------
__global__ void __launch_bounds__(128)
kC() {
    int bx = blockIdx.x;
    int s  = bx >> 4;
    int r  = bx & 15;
    int g  = r >> 2;          // ci group 0..3
    int cc = r & 3;           // p chunk
    int p0 = (cc < 2) ? cc*29 : 58 + (cc-2)*28;
    int CH = (cc < 2) ? 29 : 28;
    int d0 = p0 * 5;
    int span = (CH-1)*5 + KP; // 161 or 156

    __shared__ float xs[CIG*XSTR];          // 1344 floats
    __shared__ __align__(16) float ws[CIG*KP*16];  // 2688 floats

    int tid = threadIdx.x;
    for (int idx = tid; idx < CIG*XSTR; idx += 128) {
        int ci = idx / XSTR;
        int dd = idx - ci*XSTR;
        float v = 0.f;
        if (dd < span) v = g_x0[(s*BB + g*CIG + ci)*DM + d0 + dd];
        xs[idx] = v;
    }
    {
        const float4* wsrc = (const float4*)(g_w1ps + g*CIG*KP*16);
        float4* wdst = (float4*)ws;
        for (int idx = tid; idx < CIG*KP*4; idx += 128) wdst[idx] = wsrc[idx];
    }
    __syncthreads();

    int pt  = tid >> 3;   // 0..15 -> p pair base; warp spans 4 pt (stride-10 banks, CF)
    int cop = tid & 7;    // 0..7 co-pairs
    int pl0 = pt * 2;
    int co0 = cop * 2;
    float acc00 = 0.f, acc01 = 0.f, acc10 = 0.f, acc11 = 0.f;
    const float* xbase = xs + 5*pl0;
    #pragma unroll 2
    for (int ci = 0; ci < CIG; ci++) {
        const float* xr = xbase + ci*XSTR;
        float xw[26];
        #pragma unroll
        for (int i = 0; i < 26; i++) xw[i] = xr[i];
        const float* wp = ws + ci*(KP*16) + co0;
        #pragma unroll
        for (int m = 0; m < KP; m++) {
            float2 w = *(const float2*)(wp + m*16);
            float x0v = xw[m];
            float x1v = xw[m+5];
            acc00 += w.x * x0v;
            acc01 += w.y * x0v;
            acc10 += w.x * x1v;
            acc11 += w.y * x1v;
        }
    }
    float* dst = g_c1part + ((g*SS + s)*CO1)*P1LEN;
    if (pl0 < CH) {
        int p = p0 + pl0;
        dst[(co0  )*P1LEN + p] = acc00;
        dst[(co0+1)*P1LEN + p] = acc01;
    }
    if (pl0 + 1 < CH) {
        int p = p0 + pl0 + 1;
        dst[(co0  )*P1LEN + p] = acc10;
        dst[(co0+1)*P1LEN + p] = acc11;
    }
}

// ---------------------------------------------------------------------------
// Kernel D: assemble o1 = BN-affine(sum of 4 conv partials) + bias, then
// avgpool2 -> conv2(1x1) -> conv3(K=3, 16 channels per block) -> proj -> argmax.
// grid = 128 (64 s x 2 channel halves), block = 256.
// ---------------------------------------------------------------------------
__global__ void __launch_bounds__(256)
kD(const float* __restrict__ gamma, const float* __restrict__ beta,
   const float* __restrict__ b1,
   const float* __restrict__ w2, const float* __restrict__ b2,
   const float* __restrict__ w3, const float* __restrict__ b3,
   const float* __restrict__ wl, const float* __restrict__ bl,
   float* __restrict__ out) {
    int s   = blockIdx.x >> 1;
    int ch  = blockIdx.x & 1;
    int tid = threadIdx.x;
    __shared__ float o1[CO1*P1LEN];                  // 1824
    __shared__ __align__(16) float wls[NV*T3];       // 4608
    __shared__ float bls[NV];
    __shared__ float o2[CO2*P2LEN];                  // 304
    __shared__ float o3[16*T3];                      // 576 (this half's channels)

    // BN affine fold (redundant per thread; broadcast loads)
    float A, Cf;
    {
        float invN = 1.f / (float)(BB*DM);
        float ts = g_part[s*4 + 0] + g_part[s*4 + 2];
        float tq = g_part[s*4 + 1] + g_part[s*4 + 3];
        float m = ts * invN;
        float v = tq * invN - m*m;   // biased var, matches reference
        A = 1.f; Cf = 0.f;
        #pragma unroll
        for (int l = 0; l < NL; l++) {
            float gg = gamma[l*SS + s];
            float bb = beta[l*SS + s];
            float inv = rsqrtf(v + 1e-5f);
            float a = gg * inv;
            float c = bb - a * m;
            A = a * A;
            Cf = a * Cf + c;
            m = bb;
            v = a * a * v;
        }
    }

    // o1 assembly: affine(sum of 4 partials) + Cf*wsum + b1
    const float* pp = g_c1part + (s*CO1)*P1LEN;
    for (int i = tid; i < CO1*P1LEN; i += 256) {
        int co = i / P1LEN;
        float acc = ((pp[i] + pp[SS*CO1*P1LEN + i]) + pp[2*SS*CO1*P1LEN + i])
                    + pp[3*SS*CO1*P1LEN + i];
        o1[i] = A*acc + Cf*g_wsum1[co] + b1[co];
    }
    for (int i = tid; i < NV*T3; i += 256) wls[i] = wl[i];
    if (tid < NV) bls[tid] = bl[tid];
    __syncthreads();

    // avgpool(3) then conv2 1x1 (commutes with reference conv2->pool)
    for (int i = tid; i < CO2*P2LEN; i += 256) {
        int c8 = i / P2LEN;
        int q  = i - c8*P2LEN;
        float acc = 0.f;
        #pragma unroll
        for (int ci = 0; ci < CO1; ci++) {
            const float* rr = o1 + ci*P1LEN + 3*q;
            acc += w2[c8*CO1 + ci] * (rr[0] + rr[1] + rr[2]);
        }
        o2[i] = acc * (1.f/3.f) + b2[c8];
    }
    __syncthreads();

    // conv3 for this half's 16 channels: (8,38) -> (16,36)
    for (int i = tid; i < 16*T3; i += 256) {
        int col = i / T3;          // local channel
        int co  = ch*16 + col;
        int t   = i - col*T3;
        float acc = b3[co];
        #pragma unroll
        for (int c8 = 0; c8 < CO2; c8++) {
            const float* rr = o2 + c8*P2LEN + t;
            const float* w = w3 + (co*CO2 + c8)*3;
            acc += w[0]*rr[0] + w[1]*rr[1] + w[2]*rr[2];
        }
        o3[i] = acc;
    }
    __syncthreads();

    // projection to 128 vocab + argmax (first-max semantics like jnp.argmax)
    int c  = tid >> 4;   // local channel 0..15
    int vl = tid & 15;   // vocab lane
    float orow[T3];
    #pragma unroll
    for (int k = 0; k < T3; k++) orow[k] = o3[c*T3 + k];

    float bestv = -3.4e38f;
    int   besti = 0;
    #pragma unroll
    for (int i = 0; i < 8; i++) {
        int v = vl + 16*i;
        const float4* wr = (const float4*)(wls + v*T3);  // 36 floats = 9 float4
        float d0 = bls[v], d1 = 0.f;
        #pragma unroll
        for (int k4 = 0; k4 < 9; k4 += 2) {
            float4 w4 = wr[k4];
            d0 += orow[4*k4+0]*w4.x + orow[4*k4+1]*w4.y
                + orow[4*k4+2]*w4.z + orow[4*k4+3]*w4.w;
        }
        #pragma unroll
        for (int k4 = 1; k4 < 9; k4 += 2) {
            float4 w4 = wr[k4];
            d1 += orow[4*k4+0]*w4.x + orow[4*k4+1]*w4.y
                + orow[4*k4+2]*w4.z + orow[4*k4+3]*w4.w;
        }
        float d = d0 + d1;
        if (d > bestv) { bestv = d; besti = v; }  // strict > keeps first max in lane
    }
    #pragma unroll
    for (int off = 8; off >= 1; off >>= 1) {
        float ov = __shfl_down_sync(0xffffffffu, bestv, off);
        int   oi = __shfl_down_sync(0xffffffffu, besti, off);
        if (ov > bestv || (ov == bestv && oi < besti)) { bestv = ov; besti = oi; }
    }
    if (vl == 0) out[s*BB + ch*16 + c] = (float)besti;
}

// ---------------------------------------------------------------------------
extern "C" void kernel_launch(void* const* d_in, const int* in_sizes, int n_in,
                              void* d_out, int out_size) {
    const int*   tokens = (const int*)  d_in[0];
    const float* emb    = (const float*)d_in[1];
    const float* pos    = (const float*)d_in[2];
    const float* gamma  = (const float*)d_in[3];
    const float* beta   = (const float*)d_in[4];
    const float* w1     = (const float*)d_in[5];
    const float* b1     = (const float*)d_in[6];
    const float* w2     = (const float*)d_in[7];
    const float* b2     = (const float*)d_in[8];
    const float* w3     = (const float*)d_in[9];
    const float* b3     = (const float*)d_in[10];
    const float* wl     = (const float*)d_in[11];
    const float* bl     = (const float*)d_in[12];
    float* out = (float*)d_out;

    kS<<<2*SS + CO1, 1024>>>(tokens, emb, pos, w1);
    kC<<<1024, 128>>>();
    kD<<<128, 256>>>(gamma, beta, b1, w2, b2, w3, b3, wl, bl, out);
}